// round 3
// baseline (speedup 1.0000x reference)
#include <cuda_runtime.h>

// DeepArcNet fused kernel: 6 threads per sample (thread = token/channel),
// h[68] in registers (packed f32x2), weights via broadcast LDG,
// k/v staged per-head in static shared (<48KB). Outer loops kept rolled
// (#pragma unroll 1) to bound code size / compile time.

#define SPB 16      // samples per block
#define TPB 96      // threads per block (SPB * 6)

typedef unsigned long long ull;

// Static shared layout. xc (conv scratch) aliases kbuf: last xc read happens
// before the __syncthreads that precedes the first kbuf write.
struct SM {
  float pos[17][4];               // 272 B
  union {
    float kbuf[SPB][6 * 36];      // 13824 B  rows: tok*36 (34 used), 16B-aligned
    float xc[SPB][6][17];         // 6528 B   (conv phase only)
  };
  float vbuf[SPB][6 * 36];        // 13824 B
  float red[SPB][6][6];           // 2304 B
};                                 // total 30224 B

__device__ __forceinline__ ull pk2(float x, float y) {
  ull r; asm("mov.b64 %0, {%1,%2};" : "=l"(r) : "f"(x), "f"(y)); return r;
}
__device__ __forceinline__ void upk2(ull a, float& x, float& y) {
  asm("mov.b64 {%0,%1}, %2;" : "=f"(x), "=f"(y) : "l"(a));
}
__device__ __forceinline__ ull ffma2(ull a, ull b, ull c) {
  ull d; asm("fma.rn.f32x2 %0, %1, %2, %3;" : "=l"(d) : "l"(a), "l"(b), "l"(c)); return d;
}

__device__ __forceinline__ void pack68(const float* h, ull* hq) {
#pragma unroll
  for (int i = 0; i < 34; i++) hq[i] = pk2(h[2*i], h[2*i+1]);
}
__device__ __forceinline__ void unpack68(const ull* hq, float* h) {
#pragma unroll
  for (int i = 0; i < 34; i++) upk2(hq[i], h[2*i], h[2*i+1]);
}
__device__ __forceinline__ void pack34(const float* f, ull* fq) {
#pragma unroll
  for (int i = 0; i < 17; i++) fq[i] = pk2(f[2*i], f[2*i+1]);
}

// dot of length 68: w from global (16B-aligned rows), hq packed in regs
__device__ __forceinline__ float dot68p(const float* __restrict__ w, const ull* hq) {
  const ulonglong2* wp = reinterpret_cast<const ulonglong2*>(w);
  ull a0 = 0ull, a1 = 0ull;
#pragma unroll
  for (int i = 0; i < 17; i++) {
    ulonglong2 ww = wp[i];
    a0 = ffma2(ww.x, hq[2*i+0], a0);
    a1 = ffma2(ww.y, hq[2*i+1], a1);
  }
  float x0, y0, x1, y1; upk2(a0, x0, y0); upk2(a1, x1, y1);
  return (x0 + y0) + (x1 + y1);
}

// dot of length 34: w from global (8B-aligned rows), fq packed in regs
__device__ __forceinline__ float dot34p(const float* __restrict__ w, const ull* fq) {
  const ull* wp = reinterpret_cast<const ull*>(w);
  ull a0 = 0ull, a1 = 0ull;
#pragma unroll
  for (int i = 0; i < 16; i += 2) {
    a0 = ffma2(wp[i],   fq[i],   a0);
    a1 = ffma2(wp[i+1], fq[i+1], a1);
  }
  a0 = ffma2(wp[16], fq[16], a0);
  float x0, y0, x1, y1; upk2(a0, x0, y0); upk2(a1, x1, y1);
  return (x0 + y0) + (x1 + y1);
}

// dot of length 34: k row from shared (16B-aligned), qq packed in regs
__device__ __forceinline__ float dot34sh(const float* k, const ull* qq) {
  const ulonglong2* kp = reinterpret_cast<const ulonglong2*>(k);
  ull a0 = 0ull, a1 = 0ull;
#pragma unroll
  for (int i = 0; i < 8; i++) {
    ulonglong2 kk = kp[i];
    a0 = ffma2(kk.x, qq[2*i+0], a0);
    a1 = ffma2(kk.y, qq[2*i+1], a1);
  }
  a0 = ffma2(reinterpret_cast<const ull*>(k)[16], qq[16], a0);
  float x0, y0, x1, y1; upk2(a0, x0, y0); upk2(a1, x1, y1);
  return (x0 + y0) + (x1 + y1);
}

__device__ __forceinline__ void ln68(float* h, const float* __restrict__ g,
                                     const float* __restrict__ b) {
  float m = 0.f;
#pragma unroll
  for (int i = 0; i < 68; i++) m += h[i];
  m *= (1.0f / 68.0f);
  float v = 0.f;
#pragma unroll
  for (int i = 0; i < 68; i++) { float d = h[i] - m; v = fmaf(d, d, v); }
  v *= (1.0f / 68.0f);
  float r = rsqrtf(v + 1e-5f);
#pragma unroll
  for (int i = 0; i < 68; i++) h[i] = (h[i] - m) * r * g[i] + b[i];
}

__global__ void __launch_bounds__(TPB, 3) dan_kernel(
    const float* __restrict__ x,     const float* __restrict__ convw,
    const float* __restrict__ convb, const float* __restrict__ lembw,
    const float* __restrict__ lembb, const float* __restrict__ wq,
    const float* __restrict__ wk,    const float* __restrict__ wv,
    const float* __restrict__ projw, const float* __restrict__ projb,
    const float* __restrict__ ff1w,  const float* __restrict__ ff1b,
    const float* __restrict__ ff2w,  const float* __restrict__ ff2b,
    const float* __restrict__ ln1g,  const float* __restrict__ ln1b,
    const float* __restrict__ ln2g,  const float* __restrict__ ln2b,
    const float* __restrict__ lnfg,  const float* __restrict__ lnfb,
    const float* __restrict__ fcw,   const float* __restrict__ fcb,
    float* __restrict__ out)
{
  __shared__ SM sm;
  const int tid = threadIdx.x;
  const int samp0 = blockIdx.x * SPB;

  // sinusoidal pos table: pos[t] = [sin(t), sin(t/18), cos(t), cos(t/18)]
  if (tid < 68) {
    int t = tid >> 2, j = tid & 3;
    float ang = (j & 1) ? ((float)t * (1.0f / 18.0f)) : (float)t;
    sm.pos[t][j] = (j < 2) ? sinf(ang) : cosf(ang);
  }

  // depthwise conv 5x5 stride(2,2): xc[s][c][t] = relu(sum_{25} x * w + b)
#pragma unroll 1
  for (int o = tid; o < SPB * 102; o += TPB) {
    int s = o / 102, r = o % 102, c = r / 17, t = r % 17;
    const float* xp = x + ((size_t)(samp0 + s) * 6 + c) * 185 + t * 10;
    float acc = 0.f;
#pragma unroll
    for (int i = 0; i < 25; i++) acc = fmaf(xp[i], convw[c * 25 + i], acc);
    sm.xc[s][c][t] = fmaxf(acc + convb[c], 0.f);
  }
  __syncthreads();

  const int s = tid / 6, tok = tid - s * 6;

  // build h[68] = xc * lemb_w + lemb_b + pos, keep packed
  ull hq[34];
  {
    float h0[68];
    float lw[4], lb[4];
#pragma unroll
    for (int j = 0; j < 4; j++) { lw[j] = lembw[tok*4+j]; lb[j] = lembb[tok*4+j]; }
#pragma unroll 1
    for (int t = 0; t < 17; t++) {
      float xv = sm.xc[s][tok][t];
#pragma unroll
      for (int j = 0; j < 4; j++)
        h0[t*4+j] = fmaf(xv, lw[j], lb[j]) + sm.pos[t][j];
    }
    pack68(h0, hq);
  }

  float a[68];  // attention output (both heads), then reused

#pragma unroll 1
  for (int l = 0; l < 2; l++) {
    // ---- attention, one head at a time ----
#pragma unroll 1
    for (int hh = 0; hh < 2; hh++) {
      const float* wql = wq + l * 4624 + hh * 34 * 68;
      const float* wkl = wk + l * 4624 + hh * 34 * 68;
      const float* wvl = wv + l * 4624 + hh * 34 * 68;

      // q for this head (registers)
      float qv[34];
#pragma unroll 1
      for (int d = 0; d < 34; d++) qv[d] = dot68p(wql + d * 68, hq);
      ull qq[17];
      pack34(qv, qq);

      __syncthreads();  // prior users of kbuf/vbuf (or xc) are done

      // k, v for this head -> shared
      float* krow = &sm.kbuf[s][tok * 36];
      float* vrow = &sm.vbuf[s][tok * 36];
#pragma unroll 1
      for (int d = 0; d < 34; d++) {
        krow[d] = dot68p(wkl + d * 68, hq);
        vrow[d] = dot68p(wvl + d * 68, hq);
      }
      __syncthreads();

      // scores, softmax, weighted V
      float sc[6];
#pragma unroll 1
      for (int t2 = 0; t2 < 6; t2++)
        sc[t2] = dot34sh(&sm.kbuf[s][t2 * 36], qq) * 0.17149858514f; // 34^-0.5
      float mx = sc[0];
#pragma unroll
      for (int t2 = 1; t2 < 6; t2++) mx = fmaxf(mx, sc[t2]);
      float ssum = 0.f;
#pragma unroll
      for (int t2 = 0; t2 < 6; t2++) { sc[t2] = __expf(sc[t2] - mx); ssum += sc[t2]; }
      float inv = 1.0f / ssum;
      ull o2[17];
#pragma unroll
      for (int i = 0; i < 17; i++) o2[i] = 0ull;
#pragma unroll 1
      for (int t2 = 0; t2 < 6; t2++) {
        ull pp = pk2(sc[t2], sc[t2]);
        const float* vr = &sm.vbuf[s][t2 * 36];
        const ulonglong2* vp = reinterpret_cast<const ulonglong2*>(vr);
#pragma unroll
        for (int i = 0; i < 8; i++) {
          ulonglong2 vv = vp[i];
          o2[2*i+0] = ffma2(pp, vv.x, o2[2*i+0]);
          o2[2*i+1] = ffma2(pp, vv.y, o2[2*i+1]);
        }
        o2[16] = ffma2(pp, reinterpret_cast<const ull*>(vr)[16], o2[16]);
      }
#pragma unroll
      for (int i = 0; i < 17; i++) {
        float fx, fy; upk2(o2[i], fx, fy);
        a[hh*34 + 2*i]     = fx * inv;
        a[hh*34 + 2*i + 1] = fy * inv;
      }
    }

    // ---- proj + residual + LN1 ----
    float h[68];
    unpack68(hq, h);
    ull aq[34];
    pack68(a, aq);
    const float* pwl = projw + l * 4624;
    const float* pbl = projb + l * 68;
#pragma unroll 1
    for (int e = 0; e < 68; e++) h[e] += dot68p(pwl + e * 68, aq) + pbl[e];
    ln68(h, ln1g + l * 68, ln1b + l * 68);

    // ---- feed-forward + residual + LN2 ----
    pack68(h, hq);
    {
      float f1[34];
      const float* f1w = ff1w + l * 2312;
      const float* f1b = ff1b + l * 34;
#pragma unroll 1
      for (int j = 0; j < 34; j++)
        f1[j] = fmaxf(dot68p(f1w + j * 68, hq) + f1b[j], 0.f);
      ull fq[17];
      pack34(f1, fq);
      const float* f2w = ff2w + l * 2312;
      const float* f2b = ff2b + l * 68;
#pragma unroll 1
      for (int e = 0; e < 68; e++) h[e] += dot34p(f2w + e * 34, fq) + f2b[e];
    }
    ln68(h, ln2g + l * 68, ln2b + l * 68);
    if (l == 1) ln68(h, lnfg, lnfb);
    pack68(h, hq);
  }

  // ---- final FC over flattened [6*68]: per-token partials, reduce via shared ----
#pragma unroll 1
  for (int o6 = 0; o6 < 6; o6++)
    sm.red[s][tok][o6] = dot68p(fcw + o6 * 408 + tok * 68, hq);
  __syncthreads();
  if (tok == 0) {
#pragma unroll 1
    for (int o6 = 0; o6 < 6; o6++) {
      float v = fcb[o6];
#pragma unroll
      for (int t2 = 0; t2 < 6; t2++) v += sm.red[s][t2][o6];
      out[(size_t)(samp0 + s) * 6 + o6] = fmaxf(v, 0.f);
    }
  }
}

extern "C" void kernel_launch(void* const* d_in, const int* in_sizes, int n_in,
                              void* d_out, int out_size) {
  const float* x     = (const float*)d_in[0];
  const float* convw = (const float*)d_in[1];
  const float* convb = (const float*)d_in[2];
  const float* lembw = (const float*)d_in[3];
  const float* lembb = (const float*)d_in[4];
  const float* wq    = (const float*)d_in[5];
  const float* wk    = (const float*)d_in[6];
  const float* wv    = (const float*)d_in[7];
  const float* projw = (const float*)d_in[8];
  const float* projb = (const float*)d_in[9];
  const float* ff1w  = (const float*)d_in[10];
  const float* ff1b  = (const float*)d_in[11];
  const float* ff2w  = (const float*)d_in[12];
  const float* ff2b  = (const float*)d_in[13];
  const float* ln1g  = (const float*)d_in[14];
  const float* ln1b  = (const float*)d_in[15];
  const float* ln2g  = (const float*)d_in[16];
  const float* ln2b  = (const float*)d_in[17];
  const float* lnfg  = (const float*)d_in[18];
  const float* lnfb  = (const float*)d_in[19];
  const float* fcw   = (const float*)d_in[20];
  const float* fcb   = (const float*)d_in[21];
  float* out = (float*)d_out;

  int B = in_sizes[0] / (6 * 37 * 5);   // 32768
  int grid = B / SPB;                   // 2048

  dan_kernel<<<grid, TPB>>>(
      x, convw, convb, lembw, lembb, wq, wk, wv, projw, projb,
      ff1w, ff1b, ff2w, ff2b, ln1g, ln1b, ln2g, ln2b, lnfg, lnfb,
      fcw, fcb, out);
}

// round 4
// speedup vs baseline: 2.1275x; 2.1275x over previous
#include <cuda_runtime.h>

// DeepArcNet fused kernel v2: 6 threads per sample (thread = token),
// h[68] in registers (packed f32x2). Weights staged per-phase into shared
// memory (coalesced LDG) and consumed via LDS broadcast, eliminating the
// 4x L1-return penalty of per-thread uniform LDG.128.

#define SPB 16      // samples per block
#define TPB 96      // threads per block (SPB * 6)

typedef unsigned long long ull;

// Static shared, 48720 B < 48KB. xc (conv scratch) aliases kbuf.
struct SM {
  float pos[17][4];               // 272 B (16B-aligned size)
  float wbuf[4624];               // 18496 B  staged weight phase
  union {
    float kbuf[SPB][6 * 36];      // 13824 B  rows tok*36 (34 used), 16B-aligned
    float xc[SPB][6][17];         // conv phase only
  };
  float vbuf[SPB][6 * 36];        // 13824 B
  float red[SPB][6][6];           // 2304 B
};

__device__ __forceinline__ ull pk2(float x, float y) {
  ull r; asm("mov.b64 %0, {%1,%2};" : "=l"(r) : "f"(x), "f"(y)); return r;
}
__device__ __forceinline__ void upk2(ull a, float& x, float& y) {
  asm("mov.b64 {%0,%1}, %2;" : "=f"(x), "=f"(y) : "l"(a));
}
__device__ __forceinline__ ull ffma2(ull a, ull b, ull c) {
  ull d; asm("fma.rn.f32x2 %0, %1, %2, %3;" : "=l"(d) : "l"(a), "l"(b), "l"(c)); return d;
}

__device__ __forceinline__ void pack68(const float* h, ull* hq) {
#pragma unroll
  for (int i = 0; i < 34; i++) hq[i] = pk2(h[2*i], h[2*i+1]);
}
__device__ __forceinline__ void unpack68(const ull* hq, float* h) {
#pragma unroll
  for (int i = 0; i < 34; i++) upk2(hq[i], h[2*i], h[2*i+1]);
}
__device__ __forceinline__ void pack34(const float* f, ull* fq) {
#pragma unroll
  for (int i = 0; i < 17; i++) fq[i] = pk2(f[2*i], f[2*i+1]);
}

// dot of length 68 against a 16B-aligned shared row (LDS.128 broadcast)
__device__ __forceinline__ float dot68s(const float* w, const ull* hq) {
  const ulonglong2* wp = reinterpret_cast<const ulonglong2*>(w);
  ull a0 = 0ull, a1 = 0ull;
#pragma unroll
  for (int i = 0; i < 17; i++) {
    ulonglong2 ww = wp[i];
    a0 = ffma2(ww.x, hq[2*i+0], a0);
    a1 = ffma2(ww.y, hq[2*i+1], a1);
  }
  float x0, y0, x1, y1; upk2(a0, x0, y0); upk2(a1, x1, y1);
  return (x0 + y0) + (x1 + y1);
}

// dot of length 34 against an 8B-aligned shared row (LDS.64 broadcast)
__device__ __forceinline__ float dot34s(const float* w, const ull* fq) {
  const ull* wp = reinterpret_cast<const ull*>(w);
  ull a0 = 0ull, a1 = 0ull;
#pragma unroll
  for (int i = 0; i < 16; i += 2) {
    a0 = ffma2(wp[i],   fq[i],   a0);
    a1 = ffma2(wp[i+1], fq[i+1], a1);
  }
  a0 = ffma2(wp[16], fq[16], a0);
  float x0, y0, x1, y1; upk2(a0, x0, y0); upk2(a1, x1, y1);
  return (x0 + y0) + (x1 + y1);
}

__device__ __forceinline__ void ln68(float* h, const float* __restrict__ g,
                                     const float* __restrict__ b) {
  float m = 0.f;
#pragma unroll
  for (int i = 0; i < 68; i++) m += h[i];
  m *= (1.0f / 68.0f);
  float v = 0.f;
#pragma unroll
  for (int i = 0; i < 68; i++) { float d = h[i] - m; v = fmaf(d, d, v); }
  v *= (1.0f / 68.0f);
  float r = rsqrtf(v + 1e-5f);
#pragma unroll
  for (int i = 0; i < 68; i++) h[i] = (h[i] - m) * r * g[i] + b[i];
}

// cooperative stage: n floats (n % 4 == 0), src/dst 16B-aligned
__device__ __forceinline__ void stage(float* dst, const float* __restrict__ src,
                                      int n, int tid) {
  const float4* s4 = reinterpret_cast<const float4*>(src);
  float4* d4 = reinterpret_cast<float4*>(dst);
#pragma unroll 1
  for (int i = tid; i < (n >> 2); i += TPB) d4[i] = s4[i];
}

__global__ void __launch_bounds__(TPB, 3) dan_kernel(
    const float* __restrict__ x,     const float* __restrict__ convw,
    const float* __restrict__ convb, const float* __restrict__ lembw,
    const float* __restrict__ lembb, const float* __restrict__ wq,
    const float* __restrict__ wk,    const float* __restrict__ wv,
    const float* __restrict__ projw, const float* __restrict__ projb,
    const float* __restrict__ ff1w,  const float* __restrict__ ff1b,
    const float* __restrict__ ff2w,  const float* __restrict__ ff2b,
    const float* __restrict__ ln1g,  const float* __restrict__ ln1b,
    const float* __restrict__ ln2g,  const float* __restrict__ ln2b,
    const float* __restrict__ lnfg,  const float* __restrict__ lnfb,
    const float* __restrict__ fcw,   const float* __restrict__ fcb,
    float* __restrict__ out)
{
  __shared__ SM sm;
  const int tid = threadIdx.x;
  const int samp0 = blockIdx.x * SPB;

  // sinusoidal pos table: pos[t] = [sin(t), sin(t/18), cos(t), cos(t/18)]
  if (tid < 68) {
    int t = tid >> 2, j = tid & 3;
    float ang = (j & 1) ? ((float)t * (1.0f / 18.0f)) : (float)t;
    sm.pos[t][j] = (j < 2) ? sinf(ang) : cosf(ang);
  }

  // depthwise conv 5x5 stride(2,2): xc[s][c][t] = relu(sum_{25} x*w + b)
#pragma unroll 1
  for (int o = tid; o < SPB * 102; o += TPB) {
    int s = o / 102, r = o % 102, c = r / 17, t = r % 17;
    const float* xp = x + ((size_t)(samp0 + s) * 6 + c) * 185 + t * 10;
    float acc = 0.f;
#pragma unroll
    for (int i = 0; i < 25; i++) acc = fmaf(xp[i], convw[c * 25 + i], acc);
    sm.xc[s][c][t] = fmaxf(acc + convb[c], 0.f);
  }
  __syncthreads();

  const int s = tid / 6, tok = tid - s * 6;

  // build h[68] = xc * lemb_w + lemb_b + pos, keep packed
  ull hq[34];
  {
    float h0[68];
    float lw[4], lb[4];
#pragma unroll
    for (int j = 0; j < 4; j++) { lw[j] = lembw[tok*4+j]; lb[j] = lembb[tok*4+j]; }
#pragma unroll 1
    for (int t = 0; t < 17; t++) {
      float xv = sm.xc[s][tok][t];
#pragma unroll
      for (int j = 0; j < 4; j++)
        h0[t*4+j] = fmaf(xv, lw[j], lb[j]) + sm.pos[t][j];
    }
    pack68(h0, hq);
  }

  float a[68];  // q (both heads), then attention output

#pragma unroll 1
  for (int l = 0; l < 2; l++) {
    // ---- q, both heads ----
    __syncthreads();                       // wbuf free (prev phase done)
    stage(sm.wbuf, wq + l * 4624, 4624, tid);
    __syncthreads();
#pragma unroll 1
    for (int d = 0; d < 68; d++) a[d] = dot68s(sm.wbuf + d * 68, hq);

    // ---- per head: k/v then attention ----
#pragma unroll 1
    for (int hh = 0; hh < 2; hh++) {
      __syncthreads();                     // wbuf + (head0's attn kbuf reads) done
      stage(sm.wbuf,        wk + l * 4624 + hh * 2312, 2312, tid);
      stage(sm.wbuf + 2312, wv + l * 4624 + hh * 2312, 2312, tid);
      __syncthreads();

      float* krow = &sm.kbuf[s][tok * 36];
      float* vrow = &sm.vbuf[s][tok * 36];
#pragma unroll 1
      for (int d = 0; d < 34; d++) {
        krow[d] = dot68s(sm.wbuf + d * 68, hq);
        vrow[d] = dot68s(sm.wbuf + 2312 + d * 68, hq);
      }
      __syncthreads();

      // scores, softmax, weighted V
      ull qq[17];
      pack34(a + hh * 34, qq);
      float sc[6];
#pragma unroll 1
      for (int t2 = 0; t2 < 6; t2++) {
        const ulonglong2* kp =
            reinterpret_cast<const ulonglong2*>(&sm.kbuf[s][t2 * 36]);
        ull a0 = 0ull, a1 = 0ull;
#pragma unroll
        for (int i = 0; i < 8; i++) {
          ulonglong2 kk = kp[i];
          a0 = ffma2(kk.x, qq[2*i+0], a0);
          a1 = ffma2(kk.y, qq[2*i+1], a1);
        }
        a0 = ffma2(reinterpret_cast<const ull*>(&sm.kbuf[s][t2 * 36])[16], qq[16], a0);
        float x0, y0, x1, y1; upk2(a0, x0, y0); upk2(a1, x1, y1);
        sc[t2] = ((x0 + y0) + (x1 + y1)) * 0.17149858514f;  // 34^-0.5
      }
      float mx = sc[0];
#pragma unroll
      for (int t2 = 1; t2 < 6; t2++) mx = fmaxf(mx, sc[t2]);
      float ssum = 0.f;
#pragma unroll
      for (int t2 = 0; t2 < 6; t2++) { sc[t2] = __expf(sc[t2] - mx); ssum += sc[t2]; }
      float inv = 1.0f / ssum;
      ull o2[17];
#pragma unroll
      for (int i = 0; i < 17; i++) o2[i] = 0ull;
#pragma unroll 1
      for (int t2 = 0; t2 < 6; t2++) {
        ull pp = pk2(sc[t2], sc[t2]);
        const float* vr = &sm.vbuf[s][t2 * 36];
        const ulonglong2* vp = reinterpret_cast<const ulonglong2*>(vr);
#pragma unroll
        for (int i = 0; i < 8; i++) {
          ulonglong2 vv = vp[i];
          o2[2*i+0] = ffma2(pp, vv.x, o2[2*i+0]);
          o2[2*i+1] = ffma2(pp, vv.y, o2[2*i+1]);
        }
        o2[16] = ffma2(pp, reinterpret_cast<const ull*>(vr)[16], o2[16]);
      }
#pragma unroll
      for (int i = 0; i < 17; i++) {
        float fx, fy; upk2(o2[i], fx, fy);
        a[hh*34 + 2*i]     = fx * inv;
        a[hh*34 + 2*i + 1] = fy * inv;
      }
    }

    // ---- proj + residual + LN1 ----
    __syncthreads();
    stage(sm.wbuf, projw + l * 4624, 4624, tid);
    __syncthreads();
    float h[68];
    unpack68(hq, h);
    ull aq[34];
    pack68(a, aq);
    const float* pbl = projb + l * 68;
#pragma unroll 1
    for (int e = 0; e < 68; e++) h[e] += dot68s(sm.wbuf + e * 68, aq) + pbl[e];
    ln68(h, ln1g + l * 68, ln1b + l * 68);

    // ---- feed-forward + residual + LN2 ----
    __syncthreads();
    stage(sm.wbuf,        ff1w + l * 2312, 2312, tid);
    stage(sm.wbuf + 2312, ff2w + l * 2312, 2312, tid);
    __syncthreads();
    pack68(h, hq);
    {
      float f1[34];
      const float* f1b = ff1b + l * 34;
#pragma unroll 1
      for (int j = 0; j < 34; j++)
        f1[j] = fmaxf(dot68s(sm.wbuf + j * 68, hq) + f1b[j], 0.f);
      ull fq[17];
      pack34(f1, fq);
      const float* f2b = ff2b + l * 68;
#pragma unroll 1
      for (int e = 0; e < 68; e++) h[e] += dot34s(sm.wbuf + 2312 + e * 34, fq) + f2b[e];
    }
    ln68(h, ln2g + l * 68, ln2b + l * 68);
    if (l == 1) ln68(h, lnfg, lnfb);
    pack68(h, hq);
  }

  // ---- final FC over flattened [6*68] ----
  __syncthreads();
  stage(sm.wbuf, fcw, 2448, tid);
  __syncthreads();
#pragma unroll 1
  for (int o6 = 0; o6 < 6; o6++)
    sm.red[s][tok][o6] = dot68s(sm.wbuf + o6 * 408 + tok * 68, hq);
  __syncthreads();
  if (tok == 0) {
#pragma unroll 1
    for (int o6 = 0; o6 < 6; o6++) {
      float v = fcb[o6];
#pragma unroll
      for (int t2 = 0; t2 < 6; t2++) v += sm.red[s][t2][o6];
      out[(size_t)(samp0 + s) * 6 + o6] = fmaxf(v, 0.f);
    }
  }
}

extern "C" void kernel_launch(void* const* d_in, const int* in_sizes, int n_in,
                              void* d_out, int out_size) {
  const float* x     = (const float*)d_in[0];
  const float* convw = (const float*)d_in[1];
  const float* convb = (const float*)d_in[2];
  const float* lembw = (const float*)d_in[3];
  const float* lembb = (const float*)d_in[4];
  const float* wq    = (const float*)d_in[5];
  const float* wk    = (const float*)d_in[6];
  const float* wv    = (const float*)d_in[7];
  const float* projw = (const float*)d_in[8];
  const float* projb = (const float*)d_in[9];
  const float* ff1w  = (const float*)d_in[10];
  const float* ff1b  = (const float*)d_in[11];
  const float* ff2w  = (const float*)d_in[12];
  const float* ff2b  = (const float*)d_in[13];
  const float* ln1g  = (const float*)d_in[14];
  const float* ln1b  = (const float*)d_in[15];
  const float* ln2g  = (const float*)d_in[16];
  const float* ln2b  = (const float*)d_in[17];
  const float* lnfg  = (const float*)d_in[18];
  const float* lnfb  = (const float*)d_in[19];
  const float* fcw   = (const float*)d_in[20];
  const float* fcb   = (const float*)d_in[21];
  float* out = (float*)d_out;

  int B = in_sizes[0] / (6 * 37 * 5);   // 32768
  int grid = B / SPB;                   // 2048

  dan_kernel<<<grid, TPB>>>(
      x, convw, convb, lembw, lembb, wq, wk, wv, projw, projb,
      ff1w, ff1b, ff2w, ff2b, ln1g, ln1b, ln2g, ln2b, lnfg, lnfb,
      fcw, fcb, out);
}